// round 16
// baseline (speedup 1.0000x reference)
#include <cuda_runtime.h>

#define NN 131072
#define GG 4096
#define EE 1048576
#define SS 64
#define HH 128

typedef unsigned long long ull;

// Scratch (no allocations allowed). 16B-aligned for float4 / v4-red access.
__device__ __align__(16) float  g_w_src[2][SS];     // W @ att_src per branch
__device__ __align__(16) float  g_w_dst[2][SS];     // W @ att_dst per branch
__device__ __align__(16) float  g_a_dstv[2][GG];    // a_dst at self node of each graph
__device__ __align__(16) float  g_acc[2][GG * SS];  // sum of p * x[src] per graph (S-space)
__device__ __align__(16) float  g_denom[2][GG];     // sum of p per graph
// Packed transpose, S-MAJOR: Wt2[s*128 + c] = (Wup[s][c], Wdn[s][c]).
__device__ __align__(16) float2 g_Wt2[SS * HH];

// =========================================================================
// K1 init, grid 152 x 256 (unchanged, proven):
__global__ void init_kernel(const float* __restrict__ upW,
                            const float* __restrict__ upAs,
                            const float* __restrict__ upAd,
                            const float* __restrict__ dnW,
                            const float* __restrict__ dnAs,
                            const float* __restrict__ dnAd) {
    int t = threadIdx.x, b = blockIdx.x;
    if (b < 128) {
        float4* accv = (float4*)g_acc;               // 131072 float4 total
        const float4 z4 = make_float4(0.f, 0.f, 0.f, 0.f);
        int base = b * 1024;
#pragma unroll
        for (int i = 0; i < 4; i++) accv[base + i * 256 + t] = z4;
        if (t < 16) ((float4*)g_denom)[b * 16 + t] = z4;   // 2048 float4
    } else if (b < 144) {
        int i0 = (b - 128) * 512 + t * 2;            // 8192 float2 total
#pragma unroll
        for (int j = 0; j < 2; j++) {
            int i = i0 + j;                          // i = s*128 + c
            g_Wt2[i] = make_float2(upW[i], dnW[i]);  // same linear index
        }
    } else {
        // 8 blocks x 8 warps = 64 warps, 4 dots each -> 256 dots
        int warpId = t >> 5, lane = t & 31;
#pragma unroll
        for (int i = 0; i < 4; i++) {
            int dotId = (b - 144) * 32 + warpId * 4 + i;   // 0..255
            int vec = dotId >> 6, s = dotId & 63;          // 0 us,1 ud,2 ds,3 dd
            const float* W = (vec < 2) ? upW : dnW;
            const float* a = (vec == 0) ? upAs : (vec == 1) ? upAd
                            : (vec == 2) ? dnAs : dnAd;
            float sum = 0.f;
#pragma unroll
            for (int j = 0; j < 4; j++) {
                int h = lane + 32 * j;
                sum += W[s * HH + h] * a[h];
            }
#pragma unroll
            for (int o = 16; o; o >>= 1) sum += __shfl_xor_sync(0xffffffffu, sum, o);
            if (lane == 0) {
                float* dstp = (vec == 0) ? g_w_src[0] : (vec == 1) ? g_w_dst[0]
                             : (vec == 2) ? g_w_src[1] : g_w_dst[1];
                dstp[s] = sum;
            }
        }
    }
}

// =========================================================================
// K2: a_dst at self node (32g+31), warp per (branch, graph) (unchanged).
__global__ void dstval_kernel(const float* __restrict__ up_x,
                              const float* __restrict__ dn_x) {
    int wid = (blockIdx.x * blockDim.x + threadIdx.x) >> 5;
    int lane = threadIdx.x & 31;
    int branch = wid & 1, g = wid >> 1;
    const float* x = branch ? dn_x : up_x;
    float2 xv = *(const float2*)(x + (size_t)(g * 32 + 31) * SS + lane * 2);
    float2 wv = *(const float2*)(&g_w_dst[branch][lane * 2]);
    float s = xv.x * wv.x + xv.y * wv.y;
#pragma unroll
    for (int o = 16; o; o >>= 1) s += __shfl_xor_sync(0xffffffffu, s, o);
    if (lane == 0) g_a_dstv[branch][g] = s;
}

// =========================================================================
// K3: edge pass (unchanged, proven). Dual-edge ballot rounds.
__global__ void edge_kernel(const int* __restrict__ up_ei,
                            const int* __restrict__ dn_ei,
                            const float* __restrict__ up_x,
                            const float* __restrict__ dn_x) {
    int branch = blockIdx.y;
    const int*   ei = branch ? dn_ei : up_ei;
    const float* x  = branch ? dn_x  : up_x;
    float* acc   = g_acc[branch];
    float* denom = g_denom[branch];
    const float* adst = g_a_dstv[branch];
    int lane = threadIdx.x & 31;

    float4 wv = *(const float4*)&g_w_src[branch][(lane & 15) * 4];

    int e = blockIdx.x * blockDim.x + threadIdx.x;
    int d = ei[EE + e];                       // coalesced dst stream
    bool rel = (d & 31) == 31;
    int gph = d >> 5;
    int src = rel ? ei[e] : 0;                // lazy src load (~1/32 lanes)

    unsigned m = __ballot_sync(0xffffffffu, rel);
    while (m) {
        int lA = __ffs(m) - 1;  m &= m - 1;
        int lB = m ? (__ffs(m) - 1) : lA;
        bool two = (lB != lA);
        if (two) m &= m - 1;

        int myl = (lane < 16) ? lA : lB;
        int s2 = __shfl_sync(0xffffffffu, src, myl);
        int g2 = __shfl_sync(0xffffffffu, gph, myl);
        float ad = adst[g2];                                     // L2-resident
        float4 v = *(const float4*)(x + (size_t)s2 * SS + (lane & 15) * 4);
        float part = v.x * wv.x + v.y * wv.y + v.z * wv.z + v.w * wv.w;
#pragma unroll
        for (int o = 8; o; o >>= 1)
            part += __shfl_xor_sync(0xffffffffu, part, o);       // 16-group sum
        float ev = part + ad;
        ev = ev > 0.f ? ev : 0.2f * ev;                          // leaky_relu 0.2
        float p = __expf(ev);
        if (lane < 16 || two) {
            float* addr = acc + g2 * SS + (lane & 15) * 4;
            asm volatile("red.global.add.v4.f32 [%0], {%1,%2,%3,%4};"
                         :: "l"(addr), "f"(v.x * p), "f"(v.y * p),
                            "f"(v.z * p), "f"(v.w * p)
                         : "memory");
        }
        if (lane == 0) atomicAdd(denom + g2, p);
        if (lane == 16 && two) atomicAdd(denom + g2, p);
    }
}

// =========================================================================
// K4: epilogue as a register-tiled mini-GEMM. Grid 128 x 256.
// Block handles 32 graphs; lane = graph, warp w owns cols [16w, 16w+16).
// Weights: uniform-address broadcast LDG.128 (1 wavefront each, L1-resident)
// -> 64KB table read amortized over 32 graphs. v staged in smem s-major
// (pad 33 to dodge bank conflicts). 16 independent FFMA2 chains per lane.
// Cross-warp col reduction via smem.
__global__ void __launch_bounds__(256) final_kernel(
                             const float* __restrict__ upB,
                             const float* __restrict__ dnB,
                             const float* __restrict__ mlpW,
                             const float* __restrict__ mlpB,
                             float* __restrict__ out) {
    __shared__ __align__(16) ull vsh[SS * 33];     // vsh[s*33+g]
    __shared__ float prsh[8][32];
    int t = threadIdx.x, w = t >> 5, lane = t & 31;
    int g0 = blockIdx.x * 32;

    // ---- stage v: 2048 packed entries, coalesced g_acc reads
#pragma unroll
    for (int p = 0; p < 8; p++) {
        int g = p * 4 + (t >> 6);                 // 0..31
        int s = t & 63;
        int idx = (g0 + g) * SS + s;
        float vu = __fdividef(g_acc[0][idx], g_denom[0][g0 + g] + 1e-16f);
        float vd = __fdividef(g_acc[1][idx], g_denom[1][g0 + g] + 1e-16f);
        ull pk;
        asm("mov.b64 %0, {%1,%2};" : "=l"(pk) : "f"(vu), "f"(vd));
        vsh[s * 33 + g] = pk;
    }
    __syncthreads();

    // ---- mini-GEMM: 32 graphs (lanes) x 16 cols (this warp) x K=64
    int cbase = w * 16;
    ull acc2[16];
#pragma unroll
    for (int j = 0; j < 16; j++) acc2[j] = 0ull;

#pragma unroll 4
    for (int s = 0; s < SS; s++) {
        const ulonglong2* wrow = (const ulonglong2*)(g_Wt2 + s * HH + cbase);
        ulonglong2 w0 = wrow[0], w1 = wrow[1], w2 = wrow[2], w3 = wrow[3];
        ulonglong2 w4 = wrow[4], w5 = wrow[5], w6 = wrow[6], w7 = wrow[7];
        ull v = vsh[s * 33 + lane];
        asm("fma.rn.f32x2 %0, %1, %2, %0;" : "+l"(acc2[0])  : "l"(v), "l"(w0.x));
        asm("fma.rn.f32x2 %0, %1, %2, %0;" : "+l"(acc2[1])  : "l"(v), "l"(w0.y));
        asm("fma.rn.f32x2 %0, %1, %2, %0;" : "+l"(acc2[2])  : "l"(v), "l"(w1.x));
        asm("fma.rn.f32x2 %0, %1, %2, %0;" : "+l"(acc2[3])  : "l"(v), "l"(w1.y));
        asm("fma.rn.f32x2 %0, %1, %2, %0;" : "+l"(acc2[4])  : "l"(v), "l"(w2.x));
        asm("fma.rn.f32x2 %0, %1, %2, %0;" : "+l"(acc2[5])  : "l"(v), "l"(w2.y));
        asm("fma.rn.f32x2 %0, %1, %2, %0;" : "+l"(acc2[6])  : "l"(v), "l"(w3.x));
        asm("fma.rn.f32x2 %0, %1, %2, %0;" : "+l"(acc2[7])  : "l"(v), "l"(w3.y));
        asm("fma.rn.f32x2 %0, %1, %2, %0;" : "+l"(acc2[8])  : "l"(v), "l"(w4.x));
        asm("fma.rn.f32x2 %0, %1, %2, %0;" : "+l"(acc2[9])  : "l"(v), "l"(w4.y));
        asm("fma.rn.f32x2 %0, %1, %2, %0;" : "+l"(acc2[10]) : "l"(v), "l"(w5.x));
        asm("fma.rn.f32x2 %0, %1, %2, %0;" : "+l"(acc2[11]) : "l"(v), "l"(w5.y));
        asm("fma.rn.f32x2 %0, %1, %2, %0;" : "+l"(acc2[12]) : "l"(v), "l"(w6.x));
        asm("fma.rn.f32x2 %0, %1, %2, %0;" : "+l"(acc2[13]) : "l"(v), "l"(w6.y));
        asm("fma.rn.f32x2 %0, %1, %2, %0;" : "+l"(acc2[14]) : "l"(v), "l"(w7.x));
        asm("fma.rn.f32x2 %0, %1, %2, %0;" : "+l"(acc2[15]) : "l"(v), "l"(w7.y));
    }

    // ---- per-lane epilogue over this warp's 16 cols (uniform param loads)
    float pr = 0.f;
#pragma unroll
    for (int j = 0; j < 16; j++) {
        int c = cbase + j;
        float su, sd;
        asm("mov.b64 {%0,%1}, %2;" : "=f"(su), "=f"(sd) : "l"(acc2[j]));
        float hu = 1.f / (1.f + __expf(-(su + upB[c])));
        float hd = 1.f / (1.f + __expf(-(sd + dnB[c])));
        pr += hu * hd * mlpW[c];
    }
    prsh[w][lane] = pr;
    __syncthreads();

    // ---- cross-warp reduction: warp 0, lane = graph
    if (w == 0) {
        float sum = mlpB[0];
#pragma unroll
        for (int k = 0; k < 8; k++) sum += prsh[k][lane];
        out[g0 + lane] = sum;
    }
}

// =========================================================================
extern "C" void kernel_launch(void* const* d_in, const int* in_sizes, int n_in,
                              void* d_out, int out_size) {
    const float* up_x  = (const float*)d_in[0];
    const int*   up_ei = (const int*)d_in[1];
    const float* dn_x  = (const float*)d_in[3];
    const int*   dn_ei = (const int*)d_in[4];
    const float* upW   = (const float*)d_in[6];
    const float* upAs  = (const float*)d_in[7];
    const float* upAd  = (const float*)d_in[8];
    const float* upB   = (const float*)d_in[9];
    const float* dnW   = (const float*)d_in[10];
    const float* dnAs  = (const float*)d_in[11];
    const float* dnAd  = (const float*)d_in[12];
    const float* dnB   = (const float*)d_in[13];
    const float* mlpW  = (const float*)d_in[14];
    const float* mlpB  = (const float*)d_in[15];
    float* out = (float*)d_out;

    init_kernel<<<152, 256>>>(upW, upAs, upAd, dnW, dnAs, dnAd);
    dstval_kernel<<<1024, 256>>>(up_x, dn_x);
    dim3 egrid(EE / 256, 2);
    edge_kernel<<<egrid, 256>>>(up_ei, dn_ei, up_x, dn_x);
    final_kernel<<<GG / 32, 256>>>(upB, dnB, mlpW, mlpB, out);
}

// round 17
// speedup vs baseline: 1.4289x; 1.4289x over previous
#include <cuda_runtime.h>

#define NN 131072
#define GG 4096
#define EE 1048576
#define SS 64
#define HH 128

typedef unsigned long long ull;

// Scratch (no allocations allowed). 16B-aligned for float4 / v4-red access.
__device__ __align__(16) float  g_w_src[2][SS];     // W @ att_src per branch
__device__ __align__(16) float  g_w_dst[2][SS];     // W @ att_dst per branch
__device__ __align__(16) float  g_a_dstv[2][GG];    // a_dst at self node of each graph
__device__ __align__(16) float  g_acc[2][GG * SS];  // sum of p * x[src] per graph (S-space)
__device__ __align__(16) float  g_denom[2][GG];     // sum of p per graph
// Packed transpose, S-MAJOR: Wt2[s*128 + c] = (Wup[s][c], Wdn[s][c]).
__device__ __align__(16) float2 g_Wt2[SS * HH];

// =========================================================================
// K1 init, grid 152 x 256 (unchanged, proven):
__global__ void init_kernel(const float* __restrict__ upW,
                            const float* __restrict__ upAs,
                            const float* __restrict__ upAd,
                            const float* __restrict__ dnW,
                            const float* __restrict__ dnAs,
                            const float* __restrict__ dnAd) {
    int t = threadIdx.x, b = blockIdx.x;
    if (b < 128) {
        float4* accv = (float4*)g_acc;               // 131072 float4 total
        const float4 z4 = make_float4(0.f, 0.f, 0.f, 0.f);
        int base = b * 1024;
#pragma unroll
        for (int i = 0; i < 4; i++) accv[base + i * 256 + t] = z4;
        if (t < 16) ((float4*)g_denom)[b * 16 + t] = z4;   // 2048 float4
    } else if (b < 144) {
        int i0 = (b - 128) * 512 + t * 2;            // 8192 float2 total
#pragma unroll
        for (int j = 0; j < 2; j++) {
            int i = i0 + j;                          // i = s*128 + c
            g_Wt2[i] = make_float2(upW[i], dnW[i]);  // same linear index
        }
    } else {
        // 8 blocks x 8 warps = 64 warps, 4 dots each -> 256 dots
        int warpId = t >> 5, lane = t & 31;
#pragma unroll
        for (int i = 0; i < 4; i++) {
            int dotId = (b - 144) * 32 + warpId * 4 + i;   // 0..255
            int vec = dotId >> 6, s = dotId & 63;          // 0 us,1 ud,2 ds,3 dd
            const float* W = (vec < 2) ? upW : dnW;
            const float* a = (vec == 0) ? upAs : (vec == 1) ? upAd
                            : (vec == 2) ? dnAs : dnAd;
            float sum = 0.f;
#pragma unroll
            for (int j = 0; j < 4; j++) {
                int h = lane + 32 * j;
                sum += W[s * HH + h] * a[h];
            }
#pragma unroll
            for (int o = 16; o; o >>= 1) sum += __shfl_xor_sync(0xffffffffu, sum, o);
            if (lane == 0) {
                float* dstp = (vec == 0) ? g_w_src[0] : (vec == 1) ? g_w_dst[0]
                             : (vec == 2) ? g_w_src[1] : g_w_dst[1];
                dstp[s] = sum;
            }
        }
    }
}

// =========================================================================
// K2: a_dst at self node (32g+31), warp per (branch, graph) (unchanged).
__global__ void dstval_kernel(const float* __restrict__ up_x,
                              const float* __restrict__ dn_x) {
    int wid = (blockIdx.x * blockDim.x + threadIdx.x) >> 5;
    int lane = threadIdx.x & 31;
    int branch = wid & 1, g = wid >> 1;
    const float* x = branch ? dn_x : up_x;
    float2 xv = *(const float2*)(x + (size_t)(g * 32 + 31) * SS + lane * 2);
    float2 wv = *(const float2*)(&g_w_dst[branch][lane * 2]);
    float s = xv.x * wv.x + xv.y * wv.y;
#pragma unroll
    for (int o = 16; o; o >>= 1) s += __shfl_xor_sync(0xffffffffu, s, o);
    if (lane == 0) g_a_dstv[branch][g] = s;
}

// =========================================================================
// K3: edge pass (unchanged, proven). Dual-edge ballot rounds.
__global__ void edge_kernel(const int* __restrict__ up_ei,
                            const int* __restrict__ dn_ei,
                            const float* __restrict__ up_x,
                            const float* __restrict__ dn_x) {
    int branch = blockIdx.y;
    const int*   ei = branch ? dn_ei : up_ei;
    const float* x  = branch ? dn_x  : up_x;
    float* acc   = g_acc[branch];
    float* denom = g_denom[branch];
    const float* adst = g_a_dstv[branch];
    int lane = threadIdx.x & 31;

    float4 wv = *(const float4*)&g_w_src[branch][(lane & 15) * 4];

    int e = blockIdx.x * blockDim.x + threadIdx.x;
    int d = ei[EE + e];                       // coalesced dst stream
    bool rel = (d & 31) == 31;
    int gph = d >> 5;
    int src = rel ? ei[e] : 0;                // lazy src load (~1/32 lanes)

    unsigned m = __ballot_sync(0xffffffffu, rel);
    while (m) {
        int lA = __ffs(m) - 1;  m &= m - 1;
        int lB = m ? (__ffs(m) - 1) : lA;
        bool two = (lB != lA);
        if (two) m &= m - 1;

        int myl = (lane < 16) ? lA : lB;
        int s2 = __shfl_sync(0xffffffffu, src, myl);
        int g2 = __shfl_sync(0xffffffffu, gph, myl);
        float ad = adst[g2];                                     // L2-resident
        float4 v = *(const float4*)(x + (size_t)s2 * SS + (lane & 15) * 4);
        float part = v.x * wv.x + v.y * wv.y + v.z * wv.z + v.w * wv.w;
#pragma unroll
        for (int o = 8; o; o >>= 1)
            part += __shfl_xor_sync(0xffffffffu, part, o);       // 16-group sum
        float ev = part + ad;
        ev = ev > 0.f ? ev : 0.2f * ev;                          // leaky_relu 0.2
        float p = __expf(ev);
        if (lane < 16 || two) {
            float* addr = acc + g2 * SS + (lane & 15) * 4;
            asm volatile("red.global.add.v4.f32 [%0], {%1,%2,%3,%4};"
                         :: "l"(addr), "f"(v.x * p), "f"(v.y * p),
                            "f"(v.z * p), "f"(v.w * p)
                         : "memory");
        }
        if (lane == 0) atomicAdd(denom + g2, p);
        if (lane == 16 && two) atomicAdd(denom + g2, p);
    }
}

// =========================================================================
// K4: epilogue as flat data-parallel matvec. Grid 1024 x 256 (~7 blk/SM).
// Block = 4 graphs. Thread = (graph t>>6, column-pair {c, c+64}, c = t&63).
// Per iter: 1 uniform LDS (v) + 2 coalesced LDG.64 (Wt2 row) + 2 FFMA2
// into 2 independent chains (~30 regs -> unroll keeps loads in flight).
// Then sigmoid/product/MLP-dot; reduce 64 threads (2 warps) per graph.
__global__ void __launch_bounds__(256) final_kernel(
                             const float* __restrict__ upB,
                             const float* __restrict__ dnB,
                             const float* __restrict__ mlpW,
                             const float* __restrict__ mlpB,
                             float* __restrict__ out) {
    __shared__ __align__(16) ull vsh[4 * SS];    // 4 graphs x 64 packed (2KB)
    __shared__ float prsh[4][2];
    int t = threadIdx.x;
    int g0 = blockIdx.x * 4;

    {   // stage v: thread -> (graph t>>6, s t&63); coalesced g_acc reads
        int g = t >> 6, s = t & 63;
        int idx = (g0 + g) * SS + s;
        float vu = __fdividef(g_acc[0][idx], g_denom[0][g0 + g] + 1e-16f);
        float vd = __fdividef(g_acc[1][idx], g_denom[1][g0 + g] + 1e-16f);
        ull pk;
        asm("mov.b64 %0, {%1,%2};" : "=l"(pk) : "f"(vu), "f"(vd));
        vsh[t] = pk;
    }
    __syncthreads();

    int gl = t >> 6;            // graph within block
    int c  = t & 63;            // columns c and c+64
    const ull* vrow = &vsh[gl * SS];
    ull a0 = 0ull, a1 = 0ull;
#pragma unroll 8
    for (int s = 0; s < SS; s++) {
        ull v  = vrow[s];                                   // LDS.64 broadcast
        ull w0 = *(const ull*)&g_Wt2[s * HH + c];           // coalesced LDG.64
        ull w1 = *(const ull*)&g_Wt2[s * HH + c + 64];
        asm("fma.rn.f32x2 %0, %1, %2, %0;" : "+l"(a0) : "l"(v), "l"(w0));
        asm("fma.rn.f32x2 %0, %1, %2, %0;" : "+l"(a1) : "l"(v), "l"(w1));
    }

    float pr = 0.f;
#pragma unroll
    for (int k = 0; k < 2; k++) {
        int cc = c + 64 * k;
        float su, sd;
        asm("mov.b64 {%0,%1}, %2;" : "=f"(su), "=f"(sd) : "l"(k ? a1 : a0));
        float hu = 1.f / (1.f + __expf(-(su + upB[cc])));
        float hd = 1.f / (1.f + __expf(-(sd + dnB[cc])));
        pr += hu * hd * mlpW[cc];
    }
#pragma unroll
    for (int o = 16; o; o >>= 1) pr += __shfl_xor_sync(0xffffffffu, pr, o);
    if ((t & 31) == 0) prsh[gl][(t >> 5) & 1] = pr;
    __syncthreads();
    if (t < 4) out[g0 + t] = prsh[t][0] + prsh[t][1] + mlpB[0];
}

// =========================================================================
extern "C" void kernel_launch(void* const* d_in, const int* in_sizes, int n_in,
                              void* d_out, int out_size) {
    const float* up_x  = (const float*)d_in[0];
    const int*   up_ei = (const int*)d_in[1];
    const float* dn_x  = (const float*)d_in[3];
    const int*   dn_ei = (const int*)d_in[4];
    const float* upW   = (const float*)d_in[6];
    const float* upAs  = (const float*)d_in[7];
    const float* upAd  = (const float*)d_in[8];
    const float* upB   = (const float*)d_in[9];
    const float* dnW   = (const float*)d_in[10];
    const float* dnAs  = (const float*)d_in[11];
    const float* dnAd  = (const float*)d_in[12];
    const float* dnB   = (const float*)d_in[13];
    const float* mlpW  = (const float*)d_in[14];
    const float* mlpB  = (const float*)d_in[15];
    float* out = (float*)d_out;

    init_kernel<<<152, 256>>>(upW, upAs, upAd, dnW, dnAs, dnAd);
    dstval_kernel<<<1024, 256>>>(up_x, dn_x);
    dim3 egrid(EE / 256, 2);
    edge_kernel<<<egrid, 256>>>(up_ei, dn_ei, up_x, dn_x);
    final_kernel<<<GG / 4, 256>>>(upB, dnB, mlpW, mlpB, out);
}